// round 1
// baseline (speedup 1.0000x reference)
#include <cuda_runtime.h>
#include <cuda_bf16.h>
#include <math.h>

// Problem constants
#define B_  32
#define T_  64
#define S_  64
#define V_  32000
#define E_  512
#define H_  512
#define SD_ 1024
#define SCALE_ 0.04419417382415922f  // 1/sqrt(512)

// -------- device scratch (static; no allocations allowed) --------
__device__ float g_h[2][B_ * H_];      // ping-pong hidden state
__device__ float g_c[B_ * H_];         // cell state
__device__ float g_hhat[B_ * H_];      // input-feed vector
__device__ float g_keyp[B_ * SD_];     // attention key
__device__ float g_ct[B_ * SD_];       // attention context
__device__ float g_outs[T_ * B_ * H_]; // all h_hat outputs [t][b][h]

__device__ __forceinline__ float sigmoidf_(float x) {
    return 1.0f / (1.0f + __expf(-x));
}

// ---------------- init: broadcast initial states ----------------
__global__ void init_kernel(const float* __restrict__ hinit,
                            const float* __restrict__ iff) {
    int idx = blockIdx.x * blockDim.x + threadIdx.x;
    if (idx < B_ * H_) {
        int m = idx & (H_ - 1);
        g_h[0][idx] = hinit[m];
        g_c[idx]    = hinit[H_ + m];
        g_hhat[idx] = iff[m];
    }
}

// ---------------- fused LSTM gates + cell update ----------------
// grid 256 blocks x 256 threads. Block handles 2 hidden indices (m0, m0+1);
// warp w: gate = w&3 (i,f,g,o), m = m0 + (w>>2), column j = gate*H + m.
__global__ void __launch_bounds__(256) lstm_kernel(
    const int* __restrict__ trg, const float* __restrict__ emb,
    const float* __restrict__ W_ih, const float* __restrict__ b_ih,
    const float* __restrict__ W_hh, const float* __restrict__ b_hh,
    int t)
{
    __shared__ float gs[8][B_];
    const int w = threadIdx.x >> 5, lane = threadIdx.x & 31;
    const int gate = w & 3, m_local = w >> 2;
    const int m = blockIdx.x * 2 + m_local;
    const int j = gate * H_ + m;

    const int hb = t & 1;
    const float* __restrict__ h_in = g_h[hb];
    float* __restrict__ h_out = g_h[hb ^ 1];

    const float4* Wi = (const float4*)(W_ih + (size_t)j * (E_ + H_));
    const float4* Wh = (const float4*)(W_hh + (size_t)j * H_);

    for (int b = 0; b < B_; ++b) {
        int tok = trg[b * T_ + t];
        const float4* xe = (const float4*)(emb + (size_t)tok * E_);
        const float4* hh = (const float4*)(g_hhat + b * H_);
        const float4* hp = (const float4*)(h_in + b * H_);
        float acc = 0.f;
        #pragma unroll
        for (int i = lane; i < E_ / 4; i += 32) {
            float4 a = xe[i], ww = Wi[i];
            acc += a.x * ww.x + a.y * ww.y + a.z * ww.z + a.w * ww.w;
        }
        #pragma unroll
        for (int i = lane; i < H_ / 4; i += 32) {
            float4 a = hh[i], ww = Wi[E_ / 4 + i];
            acc += a.x * ww.x + a.y * ww.y + a.z * ww.z + a.w * ww.w;
        }
        #pragma unroll
        for (int i = lane; i < H_ / 4; i += 32) {
            float4 a = hp[i], ww = Wh[i];
            acc += a.x * ww.x + a.y * ww.y + a.z * ww.z + a.w * ww.w;
        }
        #pragma unroll
        for (int o = 16; o; o >>= 1) acc += __shfl_xor_sync(0xFFFFFFFFu, acc, o);
        if (lane == 0) gs[w][b] = acc + b_ih[j] + b_hh[j];
    }
    __syncthreads();

    if (threadIdx.x < 64) {
        int ml = threadIdx.x >> 5;
        int b  = threadIdx.x & 31;
        int m2 = blockIdx.x * 2 + ml;
        float ig = sigmoidf_(gs[ml * 4 + 0][b]);
        float fg = sigmoidf_(gs[ml * 4 + 1][b]);
        float gg = tanhf   (gs[ml * 4 + 2][b]);
        float og = sigmoidf_(gs[ml * 4 + 3][b]);
        float cn = fg * g_c[b * H_ + m2] + ig * gg;
        g_c[b * H_ + m2] = cn;
        h_out[b * H_ + m2] = og * tanhf(cn);
    }
}

// ---------------- key_p = h @ Wp^T + bp ----------------
// grid 128 x 256; warp per output column j in [0,1024)
__global__ void __launch_bounds__(256) keyp_kernel(
    const float* __restrict__ Wp, const float* __restrict__ bp, int t)
{
    const int w = threadIdx.x >> 5, lane = threadIdx.x & 31;
    const int j = blockIdx.x * 8 + w;
    const float* __restrict__ h = g_h[(t + 1) & 1];
    const float4* Wr = (const float4*)(Wp + (size_t)j * H_);
    for (int b = 0; b < B_; ++b) {
        const float4* hv = (const float4*)(h + b * H_);
        float acc = 0.f;
        #pragma unroll
        for (int i = lane; i < H_ / 4; i += 32) {
            float4 a = hv[i], ww = Wr[i];
            acc += a.x * ww.x + a.y * ww.y + a.z * ww.z + a.w * ww.w;
        }
        #pragma unroll
        for (int o = 16; o; o >>= 1) acc += __shfl_xor_sync(0xFFFFFFFFu, acc, o);
        if (lane == 0) g_keyp[b * SD_ + j] = acc + bp[j];
    }
}

// ---------------- attention: scores -> softmax -> context ----------------
// one block per batch, 512 threads (16 warps)
__global__ void __launch_bounds__(512) attn_kernel(const float* __restrict__ src)
{
    const int b = blockIdx.x;
    __shared__ float sc[S_];
    const int w = threadIdx.x >> 5, lane = threadIdx.x & 31;
    const float4* kp = (const float4*)(g_keyp + b * SD_);

    for (int s = w; s < S_; s += 16) {
        const float4* sr = (const float4*)(src + ((size_t)b * S_ + s) * SD_);
        float acc = 0.f;
        #pragma unroll
        for (int i = lane; i < SD_ / 4; i += 32) {
            float4 a = kp[i], x = sr[i];
            acc += a.x * x.x + a.y * x.y + a.z * x.z + a.w * x.w;
        }
        #pragma unroll
        for (int o = 16; o; o >>= 1) acc += __shfl_xor_sync(0xFFFFFFFFu, acc, o);
        if (lane == 0) sc[s] = acc * SCALE_;
    }
    __syncthreads();

    if (w == 0) {
        float v0 = sc[lane], v1 = sc[lane + 32];
        float mx = fmaxf(v0, v1);
        #pragma unroll
        for (int o = 16; o; o >>= 1) mx = fmaxf(mx, __shfl_xor_sync(0xFFFFFFFFu, mx, o));
        float e0 = __expf(v0 - mx), e1 = __expf(v1 - mx);
        float sm = e0 + e1;
        #pragma unroll
        for (int o = 16; o; o >>= 1) sm += __shfl_xor_sync(0xFFFFFFFFu, sm, o);
        float inv = 1.0f / sm;
        sc[lane] = e0 * inv;
        sc[lane + 32] = e1 * inv;
    }
    __syncthreads();

    for (int d = threadIdx.x; d < SD_; d += 512) {
        float acc = 0.f;
        #pragma unroll 8
        for (int s = 0; s < S_; ++s)
            acc += sc[s] * src[((size_t)b * S_ + s) * SD_ + d];
        g_ct[b * SD_ + d] = acc;
    }
}

// ---------------- h_hat = tanh([h, c_t] @ Wah^T + bah) ----------------
// grid 64 x 256; warp per output column j in [0,512)
__global__ void __launch_bounds__(256) hhat_kernel(
    const float* __restrict__ Wah, const float* __restrict__ bah, int t)
{
    const int w = threadIdx.x >> 5, lane = threadIdx.x & 31;
    const int j = blockIdx.x * 8 + w;
    const float* __restrict__ h = g_h[(t + 1) & 1];
    const float4* Wr = (const float4*)(Wah + (size_t)j * (H_ + SD_));
    for (int b = 0; b < B_; ++b) {
        const float4* hv = (const float4*)(h + b * H_);
        const float4* cv = (const float4*)(g_ct + b * SD_);
        float acc = 0.f;
        #pragma unroll
        for (int i = lane; i < H_ / 4; i += 32) {
            float4 a = hv[i], ww = Wr[i];
            acc += a.x * ww.x + a.y * ww.y + a.z * ww.z + a.w * ww.w;
        }
        #pragma unroll
        for (int i = lane; i < SD_ / 4; i += 32) {
            float4 a = cv[i], ww = Wr[H_ / 4 + i];
            acc += a.x * ww.x + a.y * ww.y + a.z * ww.z + a.w * ww.w;
        }
        #pragma unroll
        for (int o = 16; o; o >>= 1) acc += __shfl_xor_sync(0xFFFFFFFFu, acc, o);
        if (lane == 0) {
            float v = tanhf(acc + bah[j]);
            g_hhat[b * H_ + j] = v;
            g_outs[((size_t)t * B_ + b) * H_ + j] = v;
        }
    }
}

// ---------------- final projection GEMM ----------------
// C[r][v] = sum_h outs[r][h] * Wfc[v][h] + bfc[v], r = t*B + b
// scattered to out[(b*T + t)*V + v]. 64x64 tile, 4x4 micro-tile, fp32.
#define BM 64
#define BN 64
#define BK 16
__global__ void __launch_bounds__(256) gemm_kernel(
    const float* __restrict__ Wfc, const float* __restrict__ bfc,
    float* __restrict__ out)
{
    __shared__ float As[BK][BM + 4];
    __shared__ float Bs[BK][BN + 4];

    const int tid = threadIdx.x;
    const int tx = tid & 15, ty = tid >> 4;
    const int r0 = blockIdx.y * BM;
    const int v0 = blockIdx.x * BN;
    const int ld_row = tid >> 2;        // 0..63
    const int ld_k   = (tid & 3) * 4;   // 0,4,8,12

    const float* __restrict__ A = g_outs;  // [2048][512]

    float acc[4][4] = {};

    for (int k0 = 0; k0 < H_; k0 += BK) {
        float4 a  = *(const float4*)&A  [(size_t)(r0 + ld_row) * H_ + k0 + ld_k];
        float4 bb = *(const float4*)&Wfc[(size_t)(v0 + ld_row) * H_ + k0 + ld_k];
        As[ld_k + 0][ld_row] = a.x;  As[ld_k + 1][ld_row] = a.y;
        As[ld_k + 2][ld_row] = a.z;  As[ld_k + 3][ld_row] = a.w;
        Bs[ld_k + 0][ld_row] = bb.x; Bs[ld_k + 1][ld_row] = bb.y;
        Bs[ld_k + 2][ld_row] = bb.z; Bs[ld_k + 3][ld_row] = bb.w;
        __syncthreads();
        #pragma unroll
        for (int k = 0; k < BK; ++k) {
            float4 av = *(const float4*)&As[k][ty * 4];
            float4 bv = *(const float4*)&Bs[k][tx * 4];
            acc[0][0] += av.x * bv.x; acc[0][1] += av.x * bv.y;
            acc[0][2] += av.x * bv.z; acc[0][3] += av.x * bv.w;
            acc[1][0] += av.y * bv.x; acc[1][1] += av.y * bv.y;
            acc[1][2] += av.y * bv.z; acc[1][3] += av.y * bv.w;
            acc[2][0] += av.z * bv.x; acc[2][1] += av.z * bv.y;
            acc[2][2] += av.z * bv.z; acc[2][3] += av.z * bv.w;
            acc[3][0] += av.w * bv.x; acc[3][1] += av.w * bv.y;
            acc[3][2] += av.w * bv.z; acc[3][3] += av.w * bv.w;
        }
        __syncthreads();
    }

    const int v = v0 + tx * 4;
    float4 bias = *(const float4*)&bfc[v];
    #pragma unroll
    for (int i = 0; i < 4; ++i) {
        int r = r0 + ty * 4 + i;
        int tt = r >> 5;        // t = r / 32
        int bb2 = r & 31;       // b = r % 32
        size_t off = ((size_t)(bb2 * T_ + tt)) * V_ + v;
        float4 res;
        res.x = acc[i][0] + bias.x;
        res.y = acc[i][1] + bias.y;
        res.z = acc[i][2] + bias.z;
        res.w = acc[i][3] + bias.w;
        *(float4*)&out[off] = res;
    }
}

// ---------------- tail: copy final h, c, h_hat ----------------
__global__ void tail_kernel(float* __restrict__ out) {
    size_t base = (size_t)B_ * T_ * V_;
    int idx = blockIdx.x * blockDim.x + threadIdx.x;
    if (idx < B_ * H_) {
        out[base + idx]               = g_h[0][idx];  // after 64 steps, h lives in buf 0
        out[base + B_ * H_ + idx]     = g_c[idx];
        out[base + 2 * B_ * H_ + idx] = g_hhat[idx];
    }
}

extern "C" void kernel_launch(void* const* d_in, const int* in_sizes, int n_in,
                              void* d_out, int out_size) {
    const float* src    = (const float*)d_in[0];
    const int*   trg    = (const int*)  d_in[1];
    const float* emb    = (const float*)d_in[2];
    const float* W_ih   = (const float*)d_in[3];
    const float* b_ih   = (const float*)d_in[4];
    const float* W_hh   = (const float*)d_in[5];
    const float* b_hh   = (const float*)d_in[6];
    const float* Wp     = (const float*)d_in[7];
    const float* bp     = (const float*)d_in[8];
    const float* Wah    = (const float*)d_in[9];
    const float* bah    = (const float*)d_in[10];
    const float* Wfc    = (const float*)d_in[11];
    const float* bfc    = (const float*)d_in[12];
    const float* iff    = (const float*)d_in[13];
    const float* hinit  = (const float*)d_in[14];
    float* out = (float*)d_out;

    init_kernel<<<32, 512>>>(hinit, iff);

    for (int t = 0; t < T_; ++t) {
        lstm_kernel<<<256, 256>>>(trg, emb, W_ih, b_ih, W_hh, b_hh, t);
        keyp_kernel<<<128, 256>>>(Wp, bp, t);
        attn_kernel<<<32, 512>>>(src);
        hhat_kernel<<<64, 256>>>(Wah, bah, t);
    }

    dim3 ggrid(V_ / BN, (T_ * B_) / BM);
    gemm_kernel<<<ggrid, 256>>>(Wfc, bfc, out);

    tail_kernel<<<32, 512>>>(out);
}

// round 2
// speedup vs baseline: 1.0007x; 1.0007x over previous
#include <cuda_runtime.h>
#include <cuda_bf16.h>
#include <math.h>

// Problem constants
#define B_  32
#define T_  64
#define S_  64
#define V_  32000
#define E_  512
#define H_  512
#define SD_ 1024
#define SCALE_ 0.04419417382415922f  // 1/sqrt(512)

// -------- device scratch (static; no allocations allowed) --------
__device__ float g_h[2][B_ * H_];      // ping-pong hidden state
__device__ float g_c[B_ * H_];         // cell state
__device__ float g_hhat[B_ * H_];      // input-feed vector
__device__ float g_keyp[B_ * SD_];     // attention key
__device__ float g_ct[B_ * SD_];       // attention context
__device__ float g_outs[T_ * B_ * H_]; // all h_hat outputs [t][b][h]

__device__ __forceinline__ float sigmoidf_(float x) {
    return 1.0f / (1.0f + __expf(-x));
}

// ---------------- init: broadcast initial states ----------------
__global__ void init_kernel(const float* __restrict__ hinit,
                            const float* __restrict__ iff) {
    int idx = blockIdx.x * blockDim.x + threadIdx.x;
    if (idx < B_ * H_) {
        int m = idx & (H_ - 1);
        g_h[0][idx] = hinit[m];
        g_c[idx]    = hinit[H_ + m];
        g_hhat[idx] = iff[m];
    }
}

// ---------------- fused LSTM gates + cell update ----------------
// grid 256 blocks x 256 threads. Block handles 2 hidden indices (m0, m0+1);
// warp w: gate = w&3 (i,f,g,o), m = m0 + (w>>2), column j = gate*H + m.
__global__ void __launch_bounds__(256) lstm_kernel(
    const int* __restrict__ trg, const float* __restrict__ emb,
    const float* __restrict__ W_ih, const float* __restrict__ b_ih,
    const float* __restrict__ W_hh, const float* __restrict__ b_hh,
    int t)
{
    __shared__ float gs[8][B_];
    const int w = threadIdx.x >> 5, lane = threadIdx.x & 31;
    const int gate = w & 3, m_local = w >> 2;
    const int m = blockIdx.x * 2 + m_local;
    const int j = gate * H_ + m;

    const int hb = t & 1;
    const float* __restrict__ h_in = g_h[hb];
    float* __restrict__ h_out = g_h[hb ^ 1];

    const float4* Wi = (const float4*)(W_ih + (size_t)j * (E_ + H_));
    const float4* Wh = (const float4*)(W_hh + (size_t)j * H_);

    for (int b = 0; b < B_; ++b) {
        int tok = trg[b * T_ + t];
        const float4* xe = (const float4*)(emb + (size_t)tok * E_);
        const float4* hh = (const float4*)(g_hhat + b * H_);
        const float4* hp = (const float4*)(h_in + b * H_);
        float acc = 0.f;
        #pragma unroll
        for (int i = lane; i < E_ / 4; i += 32) {
            float4 a = xe[i], ww = Wi[i];
            acc += a.x * ww.x + a.y * ww.y + a.z * ww.z + a.w * ww.w;
        }
        #pragma unroll
        for (int i = lane; i < H_ / 4; i += 32) {
            float4 a = hh[i], ww = Wi[E_ / 4 + i];
            acc += a.x * ww.x + a.y * ww.y + a.z * ww.z + a.w * ww.w;
        }
        #pragma unroll
        for (int i = lane; i < H_ / 4; i += 32) {
            float4 a = hp[i], ww = Wh[i];
            acc += a.x * ww.x + a.y * ww.y + a.z * ww.z + a.w * ww.w;
        }
        #pragma unroll
        for (int o = 16; o; o >>= 1) acc += __shfl_xor_sync(0xFFFFFFFFu, acc, o);
        if (lane == 0) gs[w][b] = acc + b_ih[j] + b_hh[j];
    }
    __syncthreads();

    if (threadIdx.x < 64) {
        int ml = threadIdx.x >> 5;
        int b  = threadIdx.x & 31;
        int m2 = blockIdx.x * 2 + ml;
        float ig = sigmoidf_(gs[ml * 4 + 0][b]);
        float fg = sigmoidf_(gs[ml * 4 + 1][b]);
        float gg = tanhf   (gs[ml * 4 + 2][b]);
        float og = sigmoidf_(gs[ml * 4 + 3][b]);
        float cn = fg * g_c[b * H_ + m2] + ig * gg;
        g_c[b * H_ + m2] = cn;
        h_out[b * H_ + m2] = og * tanhf(cn);
    }
}

// ---------------- key_p = h @ Wp^T + bp ----------------
// grid 128 x 256; warp per output column j in [0,1024)
__global__ void __launch_bounds__(256) keyp_kernel(
    const float* __restrict__ Wp, const float* __restrict__ bp, int t)
{
    const int w = threadIdx.x >> 5, lane = threadIdx.x & 31;
    const int j = blockIdx.x * 8 + w;
    const float* __restrict__ h = g_h[(t + 1) & 1];
    const float4* Wr = (const float4*)(Wp + (size_t)j * H_);
    for (int b = 0; b < B_; ++b) {
        const float4* hv = (const float4*)(h + b * H_);
        float acc = 0.f;
        #pragma unroll
        for (int i = lane; i < H_ / 4; i += 32) {
            float4 a = hv[i], ww = Wr[i];
            acc += a.x * ww.x + a.y * ww.y + a.z * ww.z + a.w * ww.w;
        }
        #pragma unroll
        for (int o = 16; o; o >>= 1) acc += __shfl_xor_sync(0xFFFFFFFFu, acc, o);
        if (lane == 0) g_keyp[b * SD_ + j] = acc + bp[j];
    }
}

// ---------------- attention: scores -> softmax -> context ----------------
// one block per batch, 512 threads (16 warps)
__global__ void __launch_bounds__(512) attn_kernel(const float* __restrict__ src)
{
    const int b = blockIdx.x;
    __shared__ float sc[S_];
    const int w = threadIdx.x >> 5, lane = threadIdx.x & 31;
    const float4* kp = (const float4*)(g_keyp + b * SD_);

    for (int s = w; s < S_; s += 16) {
        const float4* sr = (const float4*)(src + ((size_t)b * S_ + s) * SD_);
        float acc = 0.f;
        #pragma unroll
        for (int i = lane; i < SD_ / 4; i += 32) {
            float4 a = kp[i], x = sr[i];
            acc += a.x * x.x + a.y * x.y + a.z * x.z + a.w * x.w;
        }
        #pragma unroll
        for (int o = 16; o; o >>= 1) acc += __shfl_xor_sync(0xFFFFFFFFu, acc, o);
        if (lane == 0) sc[s] = acc * SCALE_;
    }
    __syncthreads();

    if (w == 0) {
        float v0 = sc[lane], v1 = sc[lane + 32];
        float mx = fmaxf(v0, v1);
        #pragma unroll
        for (int o = 16; o; o >>= 1) mx = fmaxf(mx, __shfl_xor_sync(0xFFFFFFFFu, mx, o));
        float e0 = __expf(v0 - mx), e1 = __expf(v1 - mx);
        float sm = e0 + e1;
        #pragma unroll
        for (int o = 16; o; o >>= 1) sm += __shfl_xor_sync(0xFFFFFFFFu, sm, o);
        float inv = 1.0f / sm;
        sc[lane] = e0 * inv;
        sc[lane + 32] = e1 * inv;
    }
    __syncthreads();

    for (int d = threadIdx.x; d < SD_; d += 512) {
        float acc = 0.f;
        #pragma unroll 8
        for (int s = 0; s < S_; ++s)
            acc += sc[s] * src[((size_t)b * S_ + s) * SD_ + d];
        g_ct[b * SD_ + d] = acc;
    }
}

// ---------------- h_hat = tanh([h, c_t] @ Wah^T + bah) ----------------
// grid 64 x 256; warp per output column j in [0,512)
__global__ void __launch_bounds__(256) hhat_kernel(
    const float* __restrict__ Wah, const float* __restrict__ bah, int t)
{
    const int w = threadIdx.x >> 5, lane = threadIdx.x & 31;
    const int j = blockIdx.x * 8 + w;
    const float* __restrict__ h = g_h[(t + 1) & 1];
    const float4* Wr = (const float4*)(Wah + (size_t)j * (H_ + SD_));
    for (int b = 0; b < B_; ++b) {
        const float4* hv = (const float4*)(h + b * H_);
        const float4* cv = (const float4*)(g_ct + b * SD_);
        float acc = 0.f;
        #pragma unroll
        for (int i = lane; i < H_ / 4; i += 32) {
            float4 a = hv[i], ww = Wr[i];
            acc += a.x * ww.x + a.y * ww.y + a.z * ww.z + a.w * ww.w;
        }
        #pragma unroll
        for (int i = lane; i < SD_ / 4; i += 32) {
            float4 a = cv[i], ww = Wr[H_ / 4 + i];
            acc += a.x * ww.x + a.y * ww.y + a.z * ww.z + a.w * ww.w;
        }
        #pragma unroll
        for (int o = 16; o; o >>= 1) acc += __shfl_xor_sync(0xFFFFFFFFu, acc, o);
        if (lane == 0) {
            float v = tanhf(acc + bah[j]);
            g_hhat[b * H_ + j] = v;
            g_outs[((size_t)t * B_ + b) * H_ + j] = v;
        }
    }
}

// ---------------- final projection GEMM ----------------
// C[r][v] = sum_h outs[r][h] * Wfc[v][h] + bfc[v], r = t*B + b
// scattered to out[(b*T + t)*V + v]. 64x64 tile, 4x4 micro-tile, fp32.
#define BM 64
#define BN 64
#define BK 16
__global__ void __launch_bounds__(256) gemm_kernel(
    const float* __restrict__ Wfc, const float* __restrict__ bfc,
    float* __restrict__ out)
{
    __shared__ float As[BK][BM + 4];
    __shared__ float Bs[BK][BN + 4];

    const int tid = threadIdx.x;
    const int tx = tid & 15, ty = tid >> 4;
    const int r0 = blockIdx.y * BM;
    const int v0 = blockIdx.x * BN;
    const int ld_row = tid >> 2;        // 0..63
    const int ld_k   = (tid & 3) * 4;   // 0,4,8,12

    const float* __restrict__ A = g_outs;  // [2048][512]

    float acc[4][4] = {};

    for (int k0 = 0; k0 < H_; k0 += BK) {
        float4 a  = *(const float4*)&A  [(size_t)(r0 + ld_row) * H_ + k0 + ld_k];
        float4 bb = *(const float4*)&Wfc[(size_t)(v0 + ld_row) * H_ + k0 + ld_k];
        As[ld_k + 0][ld_row] = a.x;  As[ld_k + 1][ld_row] = a.y;
        As[ld_k + 2][ld_row] = a.z;  As[ld_k + 3][ld_row] = a.w;
        Bs[ld_k + 0][ld_row] = bb.x; Bs[ld_k + 1][ld_row] = bb.y;
        Bs[ld_k + 2][ld_row] = bb.z; Bs[ld_k + 3][ld_row] = bb.w;
        __syncthreads();
        #pragma unroll
        for (int k = 0; k < BK; ++k) {
            float4 av = *(const float4*)&As[k][ty * 4];
            float4 bv = *(const float4*)&Bs[k][tx * 4];
            acc[0][0] += av.x * bv.x; acc[0][1] += av.x * bv.y;
            acc[0][2] += av.x * bv.z; acc[0][3] += av.x * bv.w;
            acc[1][0] += av.y * bv.x; acc[1][1] += av.y * bv.y;
            acc[1][2] += av.y * bv.z; acc[1][3] += av.y * bv.w;
            acc[2][0] += av.z * bv.x; acc[2][1] += av.z * bv.y;
            acc[2][2] += av.z * bv.z; acc[2][3] += av.z * bv.w;
            acc[3][0] += av.w * bv.x; acc[3][1] += av.w * bv.y;
            acc[3][2] += av.w * bv.z; acc[3][3] += av.w * bv.w;
        }
        __syncthreads();
    }

    const int v = v0 + tx * 4;
    float4 bias = *(const float4*)&bfc[v];
    #pragma unroll
    for (int i = 0; i < 4; ++i) {
        int r = r0 + ty * 4 + i;
        int tt = r >> 5;        // t = r / 32
        int bb2 = r & 31;       // b = r % 32
        size_t off = ((size_t)(bb2 * T_ + tt)) * V_ + v;
        float4 res;
        res.x = acc[i][0] + bias.x;
        res.y = acc[i][1] + bias.y;
        res.z = acc[i][2] + bias.z;
        res.w = acc[i][3] + bias.w;
        *(float4*)&out[off] = res;
    }
}

// ---------------- tail: copy final h, c, h_hat ----------------
__global__ void tail_kernel(float* __restrict__ out) {
    size_t base = (size_t)B_ * T_ * V_;
    int idx = blockIdx.x * blockDim.x + threadIdx.x;
    if (idx < B_ * H_) {
        out[base + idx]               = g_h[0][idx];  // after 64 steps, h lives in buf 0
        out[base + B_ * H_ + idx]     = g_c[idx];
        out[base + 2 * B_ * H_ + idx] = g_hhat[idx];
    }
}

extern "C" void kernel_launch(void* const* d_in, const int* in_sizes, int n_in,
                              void* d_out, int out_size) {
    const float* src    = (const float*)d_in[0];
    const int*   trg    = (const int*)  d_in[1];
    const float* emb    = (const float*)d_in[2];
    const float* W_ih   = (const float*)d_in[3];
    const float* b_ih   = (const float*)d_in[4];
    const float* W_hh   = (const float*)d_in[5];
    const float* b_hh   = (const float*)d_in[6];
    const float* Wp     = (const float*)d_in[7];
    const float* bp     = (const float*)d_in[8];
    const float* Wah    = (const float*)d_in[9];
    const float* bah    = (const float*)d_in[10];
    const float* Wfc    = (const float*)d_in[11];
    const float* bfc    = (const float*)d_in[12];
    const float* iff    = (const float*)d_in[13];
    const float* hinit  = (const float*)d_in[14];
    float* out = (float*)d_out;

    init_kernel<<<32, 512>>>(hinit, iff);

    for (int t = 0; t < T_; ++t) {
        lstm_kernel<<<256, 256>>>(trg, emb, W_ih, b_ih, W_hh, b_hh, t);
        keyp_kernel<<<128, 256>>>(Wp, bp, t);
        attn_kernel<<<32, 512>>>(src);
        hhat_kernel<<<64, 256>>>(Wah, bah, t);
    }

    dim3 ggrid(V_ / BN, (T_ * B_) / BM);
    gemm_kernel<<<ggrid, 256>>>(Wfc, bfc, out);

    tail_kernel<<<32, 512>>>(out);
}